// round 15
// baseline (speedup 1.0000x reference)
#include <cuda_runtime.h>
#include <cuda_fp16.h>
#include <cstdint>

#define NMAX 100000
#define EMAX 1600000

// ---------------- device scratch -------------------------------------------
__device__ int   g_cnt[NMAX];
__device__ int   g_cur[NMAX];
__device__ int   g_off[NMAX + 1];
__device__ float g_dinv[NMAX];
__device__ int   g_srcs[EMAX];
__device__ alignas(16) float  g_bufA[(size_t)NMAX * 128];   // fp32 activations
__device__ alignas(16) __half g_bufG[(size_t)NMAX * 128];   // fp16 gather buffer
// pre-converted fp16 weight images, same [k][n] layout as fp32 source
__device__ alignas(16) __half g_W0h[128 * 128];
__device__ alignas(16) __half g_W1h[128 * 128];
__device__ alignas(16) __half g_W2h[128 * 64];

// ---------------- CSR build (R13 exact) -------------------------------------
__global__ void k_zero(int n) {
    int i = blockIdx.x * blockDim.x + threadIdx.x;
    if (i < n) { g_cnt[i] = 0; g_cur[i] = 0; }
}
__global__ void k_hist(const int* __restrict__ ei, int e, int n) {
    int i = blockIdx.x * blockDim.x + threadIdx.x;
    if (i < e) {
        int d = ei[e + i];
        if ((unsigned)d < (unsigned)n) atomicAdd(&g_cnt[d], 1);
    }
}
__global__ void k_scan(int n) {
    __shared__ int part[1024];
    int t  = threadIdx.x;
    int ch = (n + 1023) >> 10;
    int b  = t * ch;
    int en = min(n, b + ch);
    int s = 0;
    for (int i = b; i < en; i++) s += g_cnt[i];
    part[t] = s;
    __syncthreads();
    for (int off = 1; off < 1024; off <<= 1) {
        int v = (t >= off) ? part[t - off] : 0;
        __syncthreads();
        part[t] += v;
        __syncthreads();
    }
    int ex = (t == 0) ? 0 : part[t - 1];
    for (int i = b; i < en; i++) {
        g_off[i] = ex;
        int c = g_cnt[i];
        ex += c;
        g_dinv[i] = rsqrtf((float)(c + 1));
    }
    if (t == 1023) g_off[n] = part[1023];
}
__global__ void k_fill(const int* __restrict__ ei, int e, int n) {
    int i = blockIdx.x * blockDim.x + threadIdx.x;
    if (i < e) {
        int d = ei[e + i];
        int s = ei[i];
        if ((unsigned)d < (unsigned)n && (unsigned)s < (unsigned)n) {
            int pos = g_off[d] + atomicAdd(&g_cur[d], 1);
            g_srcs[pos] = s;
        }
    }
}

// -------- weight prep: fp32 -> fp16 image (same layout), once per launch ---
__global__ void k_prepW(const float* __restrict__ W, __half* __restrict__ Wh,
                        int count) {
    int i = blockIdx.x * blockDim.x + threadIdx.x;
    if (i < count / 2) {
        float2 v = ((const float2*)W)[i];
        ((__half2*)Wh)[i] = __floats2half2_rn(v.x, v.y);
    }
}

// ---------------- GEMM (HFMA2): g_bufG = fp16( dinv[row] * (X @ W) ) -------
// R13 structure exactly (KC=64 two-stage, 32KB smem); W staged from fp16
// image by straight uint2 copy instead of fp32 convert.
template <int NCOL, bool FROM_EXT>
__global__ void __launch_bounds__(256)
k_gemm(const float* __restrict__ Xext, const __half* __restrict__ Wg, int n) {
    constexpr int TX  = NCOL / 4;     // 32 / 16
    constexpr int TY  = 256 / TX;     // 8  / 16
    constexpr int RPB = 4 * TY;       // 32 / 64
    constexpr int KC  = 64;

    __shared__ __half  Wh[KC * NCOL];       // 16KB / 8KB
    __shared__ __half2 Xs[RPB * 128];       // 16KB / 32KB  (splatted (h,h))

    const float4* Xsrc = FROM_EXT ? (const float4*)Xext : (const float4*)g_bufA;

    int tid  = threadIdx.x;
    int row0 = blockIdx.x * RPB;

    // stage X: fp32 -> splatted half2 per element
    for (int i = tid; i < RPB * 32; i += 256) {
        int r = i >> 5, c = i & 31;
        int gr = row0 + r;
        float4 v = (gr < n) ? Xsrc[(size_t)gr * 32 + c]
                            : make_float4(0.f, 0.f, 0.f, 0.f);
        __half h0 = __float2half_rn(v.x), h1 = __float2half_rn(v.y);
        __half h2 = __float2half_rn(v.z), h3 = __float2half_rn(v.w);
        __half2 s0 = __halves2half2(h0, h0), s1 = __halves2half2(h1, h1);
        __half2 s2 = __halves2half2(h2, h2), s3 = __halves2half2(h3, h3);
        uint4 pk = make_uint4(*(uint32_t*)&s0, *(uint32_t*)&s1,
                              *(uint32_t*)&s2, *(uint32_t*)&s3);
        ((uint4*)Xs)[i] = pk;
    }

    int tx = tid % TX, ty = tid / TX;
    int rbase = ty * 4;

    float acc32[4][4];
#pragma unroll
    for (int r = 0; r < 4; r++)
#pragma unroll
        for (int c = 0; c < 4; c++) acc32[r][c] = 0.f;

    __half2 acch[4][2];
#pragma unroll
    for (int r = 0; r < 4; r++) {
        acch[r][0] = __halves2half2(__float2half(0.f), __float2half(0.f));
        acch[r][1] = acch[r][0];
    }

    for (int kc = 0; kc < 128; kc += KC) {
        __syncthreads();
        // stage W chunk: straight uint2 copy from fp16 image
        for (int i = tid; i < KC * NCOL / 4; i += 256)
            ((uint2*)Wh)[i] = ((const uint2*)Wg)[kc * (NCOL / 4) + i];
        __syncthreads();

#pragma unroll
        for (int k4 = 0; k4 < KC; k4 += 4) {
            uint4 a[4];
#pragma unroll
            for (int r = 0; r < 4; r++)
                a[r] = ((uint4*)Xs)[(rbase + r) * 32 + ((kc + k4) >> 2)];
#pragma unroll
            for (int kk = 0; kk < 4; kk++) {
                uint2 bu = *(const uint2*)(Wh + (k4 + kk) * NCOL + tx * 4);
                __half2 b01 = *(__half2*)&bu.x;
                __half2 b23 = *(__half2*)&bu.y;
#pragma unroll
                for (int r = 0; r < 4; r++) {
                    __half2 ah = *(__half2*)(((uint32_t*)&a[r]) + kk);
                    acch[r][0] = __hfma2(ah, b01, acch[r][0]);
                    acch[r][1] = __hfma2(ah, b23, acch[r][1]);
                }
            }
            // flush fp16 chunk to fp32 every 8 k
            if ((k4 & 4) == 4) {
#pragma unroll
                for (int r = 0; r < 4; r++) {
                    float2 f01 = __half22float2(acch[r][0]);
                    float2 f23 = __half22float2(acch[r][1]);
                    acc32[r][0] += f01.x; acc32[r][1] += f01.y;
                    acc32[r][2] += f23.x; acc32[r][3] += f23.y;
                    acch[r][0] = __halves2half2(__float2half(0.f), __float2half(0.f));
                    acch[r][1] = acch[r][0];
                }
            }
        }
    }

    // epilogue: scale by dinv, write fp16 g_bufG
#pragma unroll
    for (int r = 0; r < 4; r++) {
        int gr = row0 + rbase + r;
        if (gr < n) {
            float dv = g_dinv[gr];
            half2 h01 = __floats2half2_rn(acc32[r][0] * dv, acc32[r][1] * dv);
            half2 h23 = __floats2half2_rn(acc32[r][2] * dv, acc32[r][3] * dv);
            uint2 packed = make_uint2(*(uint32_t*)&h01, *(uint32_t*)&h23);
            *(uint2*)(g_bufG + (size_t)gr * NCOL + tx * 4) = packed;
        }
    }
}

// ------- Aggregation (R13 exact): fp16 G, fp32 accumulate, fp32 bufA -------
template <bool RELU>
__global__ void k_agg128(const float* __restrict__ bias, int n) {
    int w = (blockIdx.x * blockDim.x + threadIdx.x) >> 5;
    if (w >= n) return;
    int lane = threadIdx.x & 31;
    const uint2* G = (const uint2*)g_bufG;

    float4 acc;
    {
        uint2 u = G[(size_t)w * 32 + lane];  // self loop
        float2 f01 = __half22float2(*(half2*)&u.x);
        float2 f23 = __half22float2(*(half2*)&u.y);
        acc = make_float4(f01.x, f01.y, f23.x, f23.y);
    }
    int beg = g_off[w], end = g_off[w + 1];
    int i = beg;
    for (; i + 2 <= end; i += 2) {
        int s0 = g_srcs[i], s1 = g_srcs[i + 1];
        uint2 u0 = G[(size_t)s0 * 32 + lane];
        uint2 u1 = G[(size_t)s1 * 32 + lane];
        float2 a01 = __half22float2(*(half2*)&u0.x), a23 = __half22float2(*(half2*)&u0.y);
        float2 b01 = __half22float2(*(half2*)&u1.x), b23 = __half22float2(*(half2*)&u1.y);
        acc.x += a01.x + b01.x; acc.y += a01.y + b01.y;
        acc.z += a23.x + b23.x; acc.w += a23.y + b23.y;
    }
    if (i < end) {
        int s = g_srcs[i];
        uint2 u = G[(size_t)s * 32 + lane];
        float2 f01 = __half22float2(*(half2*)&u.x);
        float2 f23 = __half22float2(*(half2*)&u.y);
        acc.x += f01.x; acc.y += f01.y; acc.z += f23.x; acc.w += f23.y;
    }
    float dv = g_dinv[w];
    float4 bb = ((const float4*)bias)[lane];
    float4 o = make_float4(acc.x * dv + bb.x, acc.y * dv + bb.y,
                           acc.z * dv + bb.z, acc.w * dv + bb.w);
    if (RELU) {
        o.x = fmaxf(o.x, 0.f); o.y = fmaxf(o.y, 0.f);
        o.z = fmaxf(o.z, 0.f); o.w = fmaxf(o.w, 0.f);
    }
    ((float4*)g_bufA)[(size_t)w * 32 + lane] = o;
}

__global__ void k_agg64(const float* __restrict__ bias, float* __restrict__ O, int n) {
    int w = (blockIdx.x * blockDim.x + threadIdx.x) >> 5;
    if (w >= n) return;
    int lane = threadIdx.x & 31;
    const uint32_t* G = (const uint32_t*)g_bufG;

    float2 acc;
    {
        uint32_t u = G[(size_t)w * 32 + lane];
        acc = __half22float2(*(half2*)&u);
    }
    int beg = g_off[w], end = g_off[w + 1];
    int i = beg;
    for (; i + 2 <= end; i += 2) {
        int s0 = g_srcs[i], s1 = g_srcs[i + 1];
        uint32_t u0 = G[(size_t)s0 * 32 + lane];
        uint32_t u1 = G[(size_t)s1 * 32 + lane];
        float2 a = __half22float2(*(half2*)&u0);
        float2 b = __half22float2(*(half2*)&u1);
        acc.x += a.x + b.x; acc.y += a.y + b.y;
    }
    if (i < end) {
        int s = g_srcs[i];
        uint32_t u = G[(size_t)s * 32 + lane];
        float2 f = __half22float2(*(half2*)&u);
        acc.x += f.x; acc.y += f.y;
    }
    float dv = g_dinv[w];
    float2 bb = ((const float2*)bias)[lane];
    float2 o = make_float2(acc.x * dv + bb.x, acc.y * dv + bb.y);
    ((float2*)O)[(size_t)w * 32 + lane] = o;
}

// ---------------- launch ----------------------------------------------------
extern "C" void kernel_launch(void* const* d_in, const int* in_sizes, int n_in,
                              void* d_out, int out_size) {
    const float* x  = (const float*)d_in[0];
    const int*   ei = (const int*)d_in[1];
    const float* W0 = (const float*)d_in[2];
    const float* b0 = (const float*)d_in[3];
    const float* W1 = (const float*)d_in[4];
    const float* b1 = (const float*)d_in[5];
    const float* W2 = (const float*)d_in[6];
    const float* b2 = (const float*)d_in[7];

    int n = in_sizes[0] / 128;   // 100000
    int e = in_sizes[1] / 2;     // 1600000

    // weight prep (once per launch, ~3us)
    k_prepW<<<(128 * 128 / 2 + 255) / 256, 256>>>(W0, g_W0h, 128 * 128);
    k_prepW<<<(128 * 128 / 2 + 255) / 256, 256>>>(W1, g_W1h, 128 * 128);
    k_prepW<<<(128 * 64 / 2 + 255) / 256, 256>>>(W2, g_W2h, 128 * 64);

    // CSR build, in-order
    k_zero<<<(n + 255) / 256, 256>>>(n);
    k_hist<<<(e + 255) / 256, 256>>>(ei, e, n);
    k_scan<<<1, 1024>>>(n);
    k_fill<<<(e + 255) / 256, 256>>>(ei, e, n);

    int aggGrid = (n + 7) / 8;

    // layer 0
    k_gemm<128, true ><<<(n + 31) / 32, 256>>>(x, g_W0h, n);
    k_agg128<true><<<aggGrid, 256>>>(b0, n);
    // layer 1
    k_gemm<128, false><<<(n + 31) / 32, 256>>>(nullptr, g_W1h, n);
    k_agg128<true><<<aggGrid, 256>>>(b1, n);
    // layer 2 (64 cols, no relu, writes d_out)
    k_gemm<64, false><<<(n + 63) / 64, 256>>>(nullptr, g_W2h, n);
    k_agg64<<<aggGrid, 256>>>(b2, (float*)d_out, n);
}

// round 16
// speedup vs baseline: 1.1747x; 1.1747x over previous
#include <cuda_runtime.h>
#include <cuda_fp16.h>
#include <cstdint>

#define NMAX 100000
#define EMAX 1600000

// ---------------- device scratch -------------------------------------------
__device__ int   g_cnt[NMAX];
__device__ int   g_cur[NMAX];
__device__ int   g_off[NMAX + 1];
__device__ float g_dinv[NMAX];
__device__ int   g_srcs[EMAX];
__device__ alignas(16) float  g_bufA[(size_t)NMAX * 128];   // fp32 activations
__device__ alignas(16) __half g_bufG[(size_t)NMAX * 128];   // fp16 gather buffer

// ---------------- CSR build (R8 exact) --------------------------------------
__global__ void k_zero(int n) {
    int i = blockIdx.x * blockDim.x + threadIdx.x;
    if (i < n) { g_cnt[i] = 0; g_cur[i] = 0; }
}
__global__ void k_hist(const int* __restrict__ ei, int e, int n) {
    int i = blockIdx.x * blockDim.x + threadIdx.x;
    if (i < e) {
        int d = ei[e + i];
        if ((unsigned)d < (unsigned)n) atomicAdd(&g_cnt[d], 1);
    }
}
__global__ void k_scan(int n) {
    __shared__ int part[1024];
    int t  = threadIdx.x;
    int ch = (n + 1023) >> 10;
    int b  = t * ch;
    int en = min(n, b + ch);
    int s = 0;
    for (int i = b; i < en; i++) s += g_cnt[i];
    part[t] = s;
    __syncthreads();
    for (int off = 1; off < 1024; off <<= 1) {
        int v = (t >= off) ? part[t - off] : 0;
        __syncthreads();
        part[t] += v;
        __syncthreads();
    }
    int ex = (t == 0) ? 0 : part[t - 1];
    for (int i = b; i < en; i++) {
        g_off[i] = ex;
        int c = g_cnt[i];
        ex += c;
        g_dinv[i] = rsqrtf((float)(c + 1));
    }
    if (t == 1023) g_off[n] = part[1023];
}
__global__ void k_fill(const int* __restrict__ ei, int e, int n) {
    int i = blockIdx.x * blockDim.x + threadIdx.x;
    if (i < e) {
        int d = ei[e + i];
        int s = ei[i];
        if ((unsigned)d < (unsigned)n && (unsigned)s < (unsigned)n) {
            int pos = g_off[d] + atomicAdd(&g_cur[d], 1);
            g_srcs[pos] = s;
        }
    }
}

// ---------------- GEMM (HFMA2): g_bufG = fp16( dinv[row] * (X @ W) ) -------
// R8 tiling: 4 rows x 4 cols per thread, KC=64, 256 threads.
// X staged as pre-splatted half2 (h,h); W staged fp16 [k][n].
// fp16 accumulation in chunks of 8 k, flushed to fp32.
template <int NCOL, bool FROM_EXT>
__global__ void __launch_bounds__(256)
k_gemm(const float* __restrict__ Xext, const float* __restrict__ W, int n) {
    constexpr int TX  = NCOL / 4;     // 32 / 16
    constexpr int TY  = 256 / TX;     // 8  / 16
    constexpr int RPB = 4 * TY;       // 32 / 64
    constexpr int KC  = 64;

    __shared__ __half  Wh[KC * NCOL];       // 16KB / 8KB
    __shared__ __half2 Xs[RPB * 128];       // 16KB / 32KB  (splatted (h,h))

    const float4* Xsrc = FROM_EXT ? (const float4*)Xext : (const float4*)g_bufA;

    int tid  = threadIdx.x;
    int row0 = blockIdx.x * RPB;

    // stage X: fp32 -> splatted half2 per element
    for (int i = tid; i < RPB * 32; i += 256) {
        int r = i >> 5, c = i & 31;
        int gr = row0 + r;
        float4 v = (gr < n) ? Xsrc[(size_t)gr * 32 + c]
                            : make_float4(0.f, 0.f, 0.f, 0.f);
        __half h0 = __float2half_rn(v.x), h1 = __float2half_rn(v.y);
        __half h2 = __float2half_rn(v.z), h3 = __float2half_rn(v.w);
        __half2 s0 = __halves2half2(h0, h0), s1 = __halves2half2(h1, h1);
        __half2 s2 = __halves2half2(h2, h2), s3 = __halves2half2(h3, h3);
        uint4 pk = make_uint4(*(uint32_t*)&s0, *(uint32_t*)&s1,
                              *(uint32_t*)&s2, *(uint32_t*)&s3);
        ((uint4*)Xs)[i] = pk;
    }

    int tx = tid % TX, ty = tid / TX;
    int rbase = ty * 4;

    float acc32[4][4];
#pragma unroll
    for (int r = 0; r < 4; r++)
#pragma unroll
        for (int c = 0; c < 4; c++) acc32[r][c] = 0.f;

    __half2 acch[4][2];
#pragma unroll
    for (int r = 0; r < 4; r++) {
        acch[r][0] = __halves2half2(__float2half(0.f), __float2half(0.f));
        acch[r][1] = acch[r][0];
    }

    for (int kc = 0; kc < 128; kc += KC) {
        __syncthreads();
        // stage W chunk: fp32 global -> fp16 smem [k][n]
        for (int i = tid; i < KC * NCOL / 4; i += 256) {
            float4 wv = ((const float4*)W)[kc * (NCOL / 4) + i];
            __half2 w01 = __floats2half2_rn(wv.x, wv.y);
            __half2 w23 = __floats2half2_rn(wv.z, wv.w);
            *(uint2*)(Wh + i * 4) = make_uint2(*(uint32_t*)&w01, *(uint32_t*)&w23);
        }
        __syncthreads();

#pragma unroll
        for (int k4 = 0; k4 < KC; k4 += 4) {
            uint4 a[4];
#pragma unroll
            for (int r = 0; r < 4; r++)
                a[r] = ((uint4*)Xs)[(rbase + r) * 32 + ((kc + k4) >> 2)];
#pragma unroll
            for (int kk = 0; kk < 4; kk++) {
                uint2 bu = *(const uint2*)(Wh + (k4 + kk) * NCOL + tx * 4);
                __half2 b01 = *(__half2*)&bu.x;
                __half2 b23 = *(__half2*)&bu.y;
#pragma unroll
                for (int r = 0; r < 4; r++) {
                    __half2 ah = *(__half2*)(((uint32_t*)&a[r]) + kk);
                    acch[r][0] = __hfma2(ah, b01, acch[r][0]);
                    acch[r][1] = __hfma2(ah, b23, acch[r][1]);
                }
            }
            // flush fp16 chunk to fp32 every 8 k (after k4 = 4, 12, 20, ...)
            if ((k4 & 4) == 4) {
#pragma unroll
                for (int r = 0; r < 4; r++) {
                    float2 f01 = __half22float2(acch[r][0]);
                    float2 f23 = __half22float2(acch[r][1]);
                    acc32[r][0] += f01.x; acc32[r][1] += f01.y;
                    acc32[r][2] += f23.x; acc32[r][3] += f23.y;
                    acch[r][0] = __halves2half2(__float2half(0.f), __float2half(0.f));
                    acch[r][1] = acch[r][0];
                }
            }
        }
    }

    // epilogue: scale by dinv, write fp16 g_bufG (R8 layout)
#pragma unroll
    for (int r = 0; r < 4; r++) {
        int gr = row0 + rbase + r;
        if (gr < n) {
            float dv = g_dinv[gr];
            half2 h01 = __floats2half2_rn(acc32[r][0] * dv, acc32[r][1] * dv);
            half2 h23 = __floats2half2_rn(acc32[r][2] * dv, acc32[r][3] * dv);
            uint2 packed = make_uint2(*(uint32_t*)&h01, *(uint32_t*)&h23);
            *(uint2*)(g_bufG + (size_t)gr * NCOL + tx * 4) = packed;
        }
    }
}

// ------- Aggregation (R8 exact): fp16 G, fp32 accumulate, fp32 bufA --------
template <bool RELU>
__global__ void k_agg128(const float* __restrict__ bias, int n) {
    int w = (blockIdx.x * blockDim.x + threadIdx.x) >> 5;
    if (w >= n) return;
    int lane = threadIdx.x & 31;
    const uint2* G = (const uint2*)g_bufG;

    float4 acc;
    {
        uint2 u = G[(size_t)w * 32 + lane];  // self loop
        float2 f01 = __half22float2(*(half2*)&u.x);
        float2 f23 = __half22float2(*(half2*)&u.y);
        acc = make_float4(f01.x, f01.y, f23.x, f23.y);
    }
    int beg = g_off[w], end = g_off[w + 1];
    int i = beg;
    for (; i + 2 <= end; i += 2) {
        int s0 = g_srcs[i], s1 = g_srcs[i + 1];
        uint2 u0 = G[(size_t)s0 * 32 + lane];
        uint2 u1 = G[(size_t)s1 * 32 + lane];
        float2 a01 = __half22float2(*(half2*)&u0.x), a23 = __half22float2(*(half2*)&u0.y);
        float2 b01 = __half22float2(*(half2*)&u1.x), b23 = __half22float2(*(half2*)&u1.y);
        acc.x += a01.x + b01.x; acc.y += a01.y + b01.y;
        acc.z += a23.x + b23.x; acc.w += a23.y + b23.y;
    }
    if (i < end) {
        int s = g_srcs[i];
        uint2 u = G[(size_t)s * 32 + lane];
        float2 f01 = __half22float2(*(half2*)&u.x);
        float2 f23 = __half22float2(*(half2*)&u.y);
        acc.x += f01.x; acc.y += f01.y; acc.z += f23.x; acc.w += f23.y;
    }
    float dv = g_dinv[w];
    float4 bb = ((const float4*)bias)[lane];
    float4 o = make_float4(acc.x * dv + bb.x, acc.y * dv + bb.y,
                           acc.z * dv + bb.z, acc.w * dv + bb.w);
    if (RELU) {
        o.x = fmaxf(o.x, 0.f); o.y = fmaxf(o.y, 0.f);
        o.z = fmaxf(o.z, 0.f); o.w = fmaxf(o.w, 0.f);
    }
    ((float4*)g_bufA)[(size_t)w * 32 + lane] = o;
}

__global__ void k_agg64(const float* __restrict__ bias, float* __restrict__ O, int n) {
    int w = (blockIdx.x * blockDim.x + threadIdx.x) >> 5;
    if (w >= n) return;
    int lane = threadIdx.x & 31;
    const uint32_t* G = (const uint32_t*)g_bufG;

    float2 acc;
    {
        uint32_t u = G[(size_t)w * 32 + lane];
        acc = __half22float2(*(half2*)&u);
    }
    int beg = g_off[w], end = g_off[w + 1];
    int i = beg;
    for (; i + 2 <= end; i += 2) {
        int s0 = g_srcs[i], s1 = g_srcs[i + 1];
        uint32_t u0 = G[(size_t)s0 * 32 + lane];
        uint32_t u1 = G[(size_t)s1 * 32 + lane];
        float2 a = __half22float2(*(half2*)&u0);
        float2 b = __half22float2(*(half2*)&u1);
        acc.x += a.x + b.x; acc.y += a.y + b.y;
    }
    if (i < end) {
        int s = g_srcs[i];
        uint32_t u = G[(size_t)s * 32 + lane];
        float2 f = __half22float2(*(half2*)&u);
        acc.x += f.x; acc.y += f.y;
    }
    float dv = g_dinv[w];
    float2 bb = ((const float2*)bias)[lane];
    float2 o = make_float2(acc.x * dv + bb.x, acc.y * dv + bb.y);
    ((float2*)O)[(size_t)w * 32 + lane] = o;
}

// ---------------- launch ----------------------------------------------------
extern "C" void kernel_launch(void* const* d_in, const int* in_sizes, int n_in,
                              void* d_out, int out_size) {
    const float* x  = (const float*)d_in[0];
    const int*   ei = (const int*)d_in[1];
    const float* W0 = (const float*)d_in[2];
    const float* b0 = (const float*)d_in[3];
    const float* W1 = (const float*)d_in[4];
    const float* b1 = (const float*)d_in[5];
    const float* W2 = (const float*)d_in[6];
    const float* b2 = (const float*)d_in[7];

    int n = in_sizes[0] / 128;   // 100000
    int e = in_sizes[1] / 2;     // 1600000

    // CSR build, in-order (R8 exact)
    k_zero<<<(n + 255) / 256, 256>>>(n);
    k_hist<<<(e + 255) / 256, 256>>>(ei, e, n);
    k_scan<<<1, 1024>>>(n);
    k_fill<<<(e + 255) / 256, 256>>>(ei, e, n);

    int aggGrid = (n + 7) / 8;

    // layer 0
    k_gemm<128, true ><<<(n + 31) / 32, 256>>>(x, W0, n);
    k_agg128<true><<<aggGrid, 256>>>(b0, n);
    // layer 1
    k_gemm<128, false><<<(n + 31) / 32, 256>>>(nullptr, W1, n);
    k_agg128<true><<<aggGrid, 256>>>(b1, n);
    // layer 2 (64 cols, no relu, writes d_out)
    k_gemm<64, false><<<(n + 63) / 64, 256>>>(nullptr, W2, n);
    k_agg64<<<aggGrid, 256>>>(b2, (float*)d_out, n);
}

// round 17
// speedup vs baseline: 1.1989x; 1.0205x over previous
#include <cuda_runtime.h>
#include <cuda_fp16.h>
#include <cstdint>

#define NMAX 100000
#define EMAX 1600000

// ---------------- device scratch -------------------------------------------
__device__ int   g_cnt[NMAX];
__device__ int   g_cur[NMAX];
__device__ int   g_off[NMAX + 1];
__device__ float g_dinv[NMAX];
__device__ int   g_srcs[EMAX];
__device__ alignas(16) float  g_bufA[(size_t)NMAX * 128];   // fp32 activations
__device__ alignas(16) __half g_bufG[(size_t)NMAX * 128];   // fp16 gather buffer

// ---------------- CSR build (R16 exact) -------------------------------------
__global__ void k_zero(int n) {
    int i = blockIdx.x * blockDim.x + threadIdx.x;
    if (i < n) { g_cnt[i] = 0; g_cur[i] = 0; }
}
__global__ void k_hist(const int* __restrict__ ei, int e, int n) {
    int i = blockIdx.x * blockDim.x + threadIdx.x;
    if (i < e) {
        int d = ei[e + i];
        if ((unsigned)d < (unsigned)n) atomicAdd(&g_cnt[d], 1);
    }
}
__global__ void k_scan(int n) {
    __shared__ int part[1024];
    int t  = threadIdx.x;
    int ch = (n + 1023) >> 10;
    int b  = t * ch;
    int en = min(n, b + ch);
    int s = 0;
    for (int i = b; i < en; i++) s += g_cnt[i];
    part[t] = s;
    __syncthreads();
    for (int off = 1; off < 1024; off <<= 1) {
        int v = (t >= off) ? part[t - off] : 0;
        __syncthreads();
        part[t] += v;
        __syncthreads();
    }
    int ex = (t == 0) ? 0 : part[t - 1];
    for (int i = b; i < en; i++) {
        g_off[i] = ex;
        int c = g_cnt[i];
        ex += c;
        g_dinv[i] = rsqrtf((float)(c + 1));
    }
    if (t == 1023) g_off[n] = part[1023];
}
__global__ void k_fill(const int* __restrict__ ei, int e, int n) {
    int i = blockIdx.x * blockDim.x + threadIdx.x;
    if (i < e) {
        int d = ei[e + i];
        int s = ei[i];
        if ((unsigned)d < (unsigned)n && (unsigned)s < (unsigned)n) {
            int pos = g_off[d] + atomicAdd(&g_cur[d], 1);
            g_srcs[pos] = s;
        }
    }
}

// ---------------- GEMM (HFMA2): g_bufG = fp16( dinv[row] * (X @ W) ) -------
// R16 structure; fp16 accumulation chunk lengthened 8k -> 16k (fewer flushes).
template <int NCOL, bool FROM_EXT>
__global__ void __launch_bounds__(256)
k_gemm(const float* __restrict__ Xext, const float* __restrict__ W, int n) {
    constexpr int TX  = NCOL / 4;     // 32 / 16
    constexpr int TY  = 256 / TX;     // 8  / 16
    constexpr int RPB = 4 * TY;       // 32 / 64
    constexpr int KC  = 64;

    __shared__ __half  Wh[KC * NCOL];       // 16KB / 8KB
    __shared__ __half2 Xs[RPB * 128];       // 16KB / 32KB  (splatted (h,h))

    const float4* Xsrc = FROM_EXT ? (const float4*)Xext : (const float4*)g_bufA;

    int tid  = threadIdx.x;
    int row0 = blockIdx.x * RPB;

    // stage X: fp32 -> splatted half2 per element
    for (int i = tid; i < RPB * 32; i += 256) {
        int r = i >> 5, c = i & 31;
        int gr = row0 + r;
        float4 v = (gr < n) ? Xsrc[(size_t)gr * 32 + c]
                            : make_float4(0.f, 0.f, 0.f, 0.f);
        __half h0 = __float2half_rn(v.x), h1 = __float2half_rn(v.y);
        __half h2 = __float2half_rn(v.z), h3 = __float2half_rn(v.w);
        __half2 s0 = __halves2half2(h0, h0), s1 = __halves2half2(h1, h1);
        __half2 s2 = __halves2half2(h2, h2), s3 = __halves2half2(h3, h3);
        uint4 pk = make_uint4(*(uint32_t*)&s0, *(uint32_t*)&s1,
                              *(uint32_t*)&s2, *(uint32_t*)&s3);
        ((uint4*)Xs)[i] = pk;
    }

    int tx = tid % TX, ty = tid / TX;
    int rbase = ty * 4;

    float acc32[4][4];
#pragma unroll
    for (int r = 0; r < 4; r++)
#pragma unroll
        for (int c = 0; c < 4; c++) acc32[r][c] = 0.f;

    __half2 acch[4][2];
#pragma unroll
    for (int r = 0; r < 4; r++) {
        acch[r][0] = __halves2half2(__float2half(0.f), __float2half(0.f));
        acch[r][1] = acch[r][0];
    }

    for (int kc = 0; kc < 128; kc += KC) {
        __syncthreads();
        // stage W chunk: fp32 global -> fp16 smem [k][n]
        for (int i = tid; i < KC * NCOL / 4; i += 256) {
            float4 wv = ((const float4*)W)[kc * (NCOL / 4) + i];
            __half2 w01 = __floats2half2_rn(wv.x, wv.y);
            __half2 w23 = __floats2half2_rn(wv.z, wv.w);
            *(uint2*)(Wh + i * 4) = make_uint2(*(uint32_t*)&w01, *(uint32_t*)&w23);
        }
        __syncthreads();

#pragma unroll
        for (int k4 = 0; k4 < KC; k4 += 4) {
            uint4 a[4];
#pragma unroll
            for (int r = 0; r < 4; r++)
                a[r] = ((uint4*)Xs)[(rbase + r) * 32 + ((kc + k4) >> 2)];
#pragma unroll
            for (int kk = 0; kk < 4; kk++) {
                uint2 bu = *(const uint2*)(Wh + (k4 + kk) * NCOL + tx * 4);
                __half2 b01 = *(__half2*)&bu.x;
                __half2 b23 = *(__half2*)&bu.y;
#pragma unroll
                for (int r = 0; r < 4; r++) {
                    __half2 ah = *(__half2*)(((uint32_t*)&a[r]) + kk);
                    acch[r][0] = __hfma2(ah, b01, acch[r][0]);
                    acch[r][1] = __hfma2(ah, b23, acch[r][1]);
                }
            }
            // flush fp16 chunk to fp32 every 16 k (after k4 = 12, 28, 44, 60)
            if ((k4 & 12) == 12) {
#pragma unroll
                for (int r = 0; r < 4; r++) {
                    float2 f01 = __half22float2(acch[r][0]);
                    float2 f23 = __half22float2(acch[r][1]);
                    acc32[r][0] += f01.x; acc32[r][1] += f01.y;
                    acc32[r][2] += f23.x; acc32[r][3] += f23.y;
                    acch[r][0] = __halves2half2(__float2half(0.f), __float2half(0.f));
                    acch[r][1] = acch[r][0];
                }
            }
        }
    }

    // epilogue: scale by dinv, write fp16 g_bufG
#pragma unroll
    for (int r = 0; r < 4; r++) {
        int gr = row0 + rbase + r;
        if (gr < n) {
            float dv = g_dinv[gr];
            half2 h01 = __floats2half2_rn(acc32[r][0] * dv, acc32[r][1] * dv);
            half2 h23 = __floats2half2_rn(acc32[r][2] * dv, acc32[r][3] * dv);
            uint2 packed = make_uint2(*(uint32_t*)&h01, *(uint32_t*)&h23);
            *(uint2*)(g_bufG + (size_t)gr * NCOL + tx * 4) = packed;
        }
    }
}

// ------- Aggregation (R16 exact): fp16 G, fp32 accumulate, fp32 bufA -------
template <bool RELU>
__global__ void k_agg128(const float* __restrict__ bias, int n) {
    int w = (blockIdx.x * blockDim.x + threadIdx.x) >> 5;
    if (w >= n) return;
    int lane = threadIdx.x & 31;
    const uint2* G = (const uint2*)g_bufG;

    float4 acc;
    {
        uint2 u = G[(size_t)w * 32 + lane];  // self loop
        float2 f01 = __half22float2(*(half2*)&u.x);
        float2 f23 = __half22float2(*(half2*)&u.y);
        acc = make_float4(f01.x, f01.y, f23.x, f23.y);
    }
    int beg = g_off[w], end = g_off[w + 1];
    int i = beg;
    for (; i + 2 <= end; i += 2) {
        int s0 = g_srcs[i], s1 = g_srcs[i + 1];
        uint2 u0 = G[(size_t)s0 * 32 + lane];
        uint2 u1 = G[(size_t)s1 * 32 + lane];
        float2 a01 = __half22float2(*(half2*)&u0.x), a23 = __half22float2(*(half2*)&u0.y);
        float2 b01 = __half22float2(*(half2*)&u1.x), b23 = __half22float2(*(half2*)&u1.y);
        acc.x += a01.x + b01.x; acc.y += a01.y + b01.y;
        acc.z += a23.x + b23.x; acc.w += a23.y + b23.y;
    }
    if (i < end) {
        int s = g_srcs[i];
        uint2 u = G[(size_t)s * 32 + lane];
        float2 f01 = __half22float2(*(half2*)&u.x);
        float2 f23 = __half22float2(*(half2*)&u.y);
        acc.x += f01.x; acc.y += f01.y; acc.z += f23.x; acc.w += f23.y;
    }
    float dv = g_dinv[w];
    float4 bb = ((const float4*)bias)[lane];
    float4 o = make_float4(acc.x * dv + bb.x, acc.y * dv + bb.y,
                           acc.z * dv + bb.z, acc.w * dv + bb.w);
    if (RELU) {
        o.x = fmaxf(o.x, 0.f); o.y = fmaxf(o.y, 0.f);
        o.z = fmaxf(o.z, 0.f); o.w = fmaxf(o.w, 0.f);
    }
    ((float4*)g_bufA)[(size_t)w * 32 + lane] = o;
}

__global__ void k_agg64(const float* __restrict__ bias, float* __restrict__ O, int n) {
    int w = (blockIdx.x * blockDim.x + threadIdx.x) >> 5;
    if (w >= n) return;
    int lane = threadIdx.x & 31;
    const uint32_t* G = (const uint32_t*)g_bufG;

    float2 acc;
    {
        uint32_t u = G[(size_t)w * 32 + lane];
        acc = __half22float2(*(half2*)&u);
    }
    int beg = g_off[w], end = g_off[w + 1];
    int i = beg;
    for (; i + 2 <= end; i += 2) {
        int s0 = g_srcs[i], s1 = g_srcs[i + 1];
        uint32_t u0 = G[(size_t)s0 * 32 + lane];
        uint32_t u1 = G[(size_t)s1 * 32 + lane];
        float2 a = __half22float2(*(half2*)&u0);
        float2 b = __half22float2(*(half2*)&u1);
        acc.x += a.x + b.x; acc.y += a.y + b.y;
    }
    if (i < end) {
        int s = g_srcs[i];
        uint32_t u = G[(size_t)s * 32 + lane];
        float2 f = __half22float2(*(half2*)&u);
        acc.x += f.x; acc.y += f.y;
    }
    float dv = g_dinv[w];
    float2 bb = ((const float2*)bias)[lane];
    float2 o = make_float2(acc.x * dv + bb.x, acc.y * dv + bb.y);
    ((float2*)O)[(size_t)w * 32 + lane] = o;
}

// ---------------- launch ----------------------------------------------------
extern "C" void kernel_launch(void* const* d_in, const int* in_sizes, int n_in,
                              void* d_out, int out_size) {
    const float* x  = (const float*)d_in[0];
    const int*   ei = (const int*)d_in[1];
    const float* W0 = (const float*)d_in[2];
    const float* b0 = (const float*)d_in[3];
    const float* W1 = (const float*)d_in[4];
    const float* b1 = (const float*)d_in[5];
    const float* W2 = (const float*)d_in[6];
    const float* b2 = (const float*)d_in[7];

    int n = in_sizes[0] / 128;   // 100000
    int e = in_sizes[1] / 2;     // 1600000

    // CSR build, in-order
    k_zero<<<(n + 255) / 256, 256>>>(n);
    k_hist<<<(e + 255) / 256, 256>>>(ei, e, n);
    k_scan<<<1, 1024>>>(n);
    k_fill<<<(e + 255) / 256, 256>>>(ei, e, n);

    int aggGrid = (n + 7) / 8;

    // layer 0
    k_gemm<128, true ><<<(n + 31) / 32, 256>>>(x, W0, n);
    k_agg128<true><<<aggGrid, 256>>>(b0, n);
    // layer 1
    k_gemm<128, false><<<(n + 31) / 32, 256>>>(nullptr, W1, n);
    k_agg128<true><<<aggGrid, 256>>>(b1, n);
    // layer 2 (64 cols, no relu, writes d_out)
    k_gemm<64, false><<<(n + 63) / 64, 256>>>(nullptr, W2, n);
    k_agg64<<<aggGrid, 256>>>(b2, (float*)d_out, n);
}